// round 11
// baseline (speedup 1.0000x reference)
#include <cuda_runtime.h>
#include <cstdint>

#define T_STEPS 300
#define E_DIM   300
#define H_DIM   512
#define G_DIM   2048   // 4*H
#define N_EXP   13
#define V_SIZE  400000
#define NCTA    64     // recurrent CTAs; 8 hidden units each
#define UNITS   8
#define NTHR    512
#define DEPTH   8      // mailbox ring depth (power of 2)
#define ROWS_PER_BLK 32
#define SENTINEL 2.0f  // |h| <= 1 always

// Scratch (device globals: no allocation allowed)
__device__ float g_gates[T_STEPS * G_DIM];                       // input gates (+biases)
__device__ __align__(16) float g_box[NCTA * DEPTH * H_DIM];      // private mailboxes, 1 MB

// ---------------------------------------------------------------------------
// Volatile global access helpers (compiler cannot hoist/elide these)
// ---------------------------------------------------------------------------
__device__ __forceinline__ float ld_vol_f(const float* p) {
    float v;
    asm volatile("ld.volatile.global.f32 %0, [%1];" : "=f"(v) : "l"(p));
    return v;
}
__device__ __forceinline__ float4 ld_vol_f4(const float4* p) {
    float4 v;
    asm volatile("ld.volatile.global.v4.f32 {%0,%1,%2,%3}, [%4];"
                 : "=f"(v.x), "=f"(v.y), "=f"(v.z), "=f"(v.w) : "l"(p));
    return v;
}
__device__ __forceinline__ void st_vol_f4(float4* p, float4 v) {
    asm volatile("st.volatile.global.v4.f32 [%0], {%1,%2,%3,%4};"
                 :: "l"(p), "f"(v.x), "f"(v.y), "f"(v.z), "f"(v.w));
}

// ---------------------------------------------------------------------------
// Kernel 1: re-init mailboxes each replay. Depth 0 = h0; others = sentinel.
// ---------------------------------------------------------------------------
__global__ void init_kernel(const float* __restrict__ h0) {
    int idx = blockIdx.x * blockDim.x + threadIdx.x;
    if (idx < NCTA * DEPTH * H_DIM) {
        int k = idx & (H_DIM - 1);
        int d = (idx >> 9) & (DEPTH - 1);
        g_box[idx] = (d == 0) ? h0[k] : SENTINEL;
    }
}

// ---------------------------------------------------------------------------
// x-buffer probe: reference declares int64 but JAX w/o x64 yields int32.
// ---------------------------------------------------------------------------
__device__ __forceinline__ bool probe_is_i64(const int* __restrict__ x32) {
    bool all_zero = true;
    #pragma unroll
    for (int i = 1; i < 64; i += 2) all_zero &= (x32[i] == 0);
    return all_zero;
}
__device__ __forceinline__ int load_token(const int* __restrict__ x32, int t, bool i64) {
    int v = i64 ? x32[2 * t] : x32[t];
    return (v < 0) ? 0 : (v >= V_SIZE ? V_SIZE - 1 : v);
}

// ---------------------------------------------------------------------------
// Kernel 2: input gates (unchanged; proven).
// ---------------------------------------------------------------------------
__global__ void __launch_bounds__(256) gates_kernel(
    const int* __restrict__ x32, const int* __restrict__ tags,
    const float* __restrict__ emb, const float* __restrict__ W_ih,
    const float* __restrict__ b_ih, const float* __restrict__ b_hh)
{
    __shared__ float sw[ROWS_PER_BLK * E_DIM];   // 37.5 KB
    __shared__ float sx[E_DIM];
    __shared__ float sb[ROWS_PER_BLK];
    __shared__ int   stags[T_STEPS];
    __shared__ int   s_i64;

    const int e     = blockIdx.x / (G_DIM / ROWS_PER_BLK);
    const int chunk = blockIdx.x % (G_DIM / ROWS_PER_BLK);
    const int row0  = chunk * ROWS_PER_BLK;
    const int tid   = threadIdx.x;

    const float* wsrc = W_ih + ((size_t)e * G_DIM + row0) * E_DIM;
    for (int i = tid; i < ROWS_PER_BLK * E_DIM; i += 256) sw[i] = wsrc[i];
    if (tid < ROWS_PER_BLK)
        sb[tid] = b_ih[e * G_DIM + row0 + tid] + b_hh[e * G_DIM + row0 + tid];
    for (int i = tid; i < T_STEPS; i += 256) stags[i] = tags[i];
    if (tid == 0) s_i64 = probe_is_i64(x32) ? 1 : 0;
    __syncthreads();

    const bool i64  = (s_i64 != 0);
    const int row   = tid >> 3;   // 0..31
    const int lane8 = tid & 7;

    for (int t = 0; t < T_STEPS; t++) {
        if (stags[t] != e) continue;                 // uniform branch (smem)
        const float* xe = emb + (size_t)load_token(x32, t, i64) * E_DIM;
        for (int i = tid; i < E_DIM; i += 256) sx[i] = xe[i];
        __syncthreads();
        float acc = 0.f;
        for (int k = lane8; k < E_DIM; k += 8)
            acc += sw[row * E_DIM + k] * sx[k];
        #pragma unroll
        for (int off = 4; off; off >>= 1)
            acc += __shfl_down_sync(0xffffffffu, acc, off, 8);
        if (lane8 == 0)
            g_gates[t * G_DIM + row0 + row] = acc + sb[row];
        __syncthreads();
    }
}

// ---------------------------------------------------------------------------
// Kernel 3: recurrent LSTM, 64 CTAs x 512 threads, private-mailbox sync.
// R10 change vs R9: poll loads are the FIRST loads each iteration for the
// poll warps; weight/gate prefetches issue after the post-staging barrier so
// they never queue ahead of the polls in L1tex.
// ---------------------------------------------------------------------------
__global__ void __launch_bounds__(NTHR, 1) lstm_kernel(
    const int* __restrict__ tags, const float* __restrict__ W_hh,
    const float* __restrict__ c0,
    const float* __restrict__ fc_w, const float* __restrict__ fc_b,
    float* __restrict__ d_out, int out_size)
{
    __shared__ __align__(16) float sh[H_DIM];   // h[s] staged
    __shared__ float ssum[32];                  // per-row dot sums
    __shared__ float sgin[2][32];               // input gates, double-buffered
    __shared__ int   stags[T_STEPS];

    const int tid    = threadIdx.x;
    const int base   = blockIdx.x * UNITS;      // first hidden unit owned
    const int rid    = tid >> 4;                // 0..31: gate row id
    const int lane16 = tid & 15;
    const int g      = rid >> 3;                // gate: 0=i 1=f 2=g 3=o
    const int u      = rid & 7;                 // unit within CTA
    const int row    = g * H_DIM + base + u;    // global gate row
    const bool pollw = ((tid >> 7) == 1);       // warps 4-7: poll/stage role

    for (int i = tid; i < T_STEPS; i += NTHR) stags[i] = tags[i];
    float cval = 0.f, hval = 0.f;
    if (tid < UNITS) cval = c0[base + tid];
    // Preload step-0 input gates into buffer 0 (warp 0)
    if (tid < 32)
        sgin[0][tid] = __ldg(&g_gates[0 * G_DIM + (tid >> 3) * H_DIM + base + (tid & 7)]);
    __syncthreads();

    // Preload step-0 weights: thread covers k = lane16*4 + 64*m, m=0..7
    float4 wc[8], wn[8];
    {
        const float4* p = (const float4*)(W_hh + ((size_t)stags[0] * G_DIM + row) * H_DIM) + lane16;
        #pragma unroll
        for (int m = 0; m < 8; m++) wc[m] = __ldg(p + m * 16);
    }

    float4* const mybox = (float4*)(g_box + (size_t)blockIdx.x * DEPTH * H_DIM);
    const float4 sent4 = make_float4(SENTINEL, SENTINEL, SENTINEL, SENTINEL);

    for (int s = 0; s < T_STEPS; s++) {
        const int sn = (s + 1 < T_STEPS) ? s + 1 : s;

        // A. Gate prefetch for s+1 (warp 0 — NOT a poll warp; off the poll path)
        float gin_next = 0.f;
        if (tid < 32)
            gin_next = __ldg(&g_gates[sn * G_DIM + (tid >> 3) * H_DIM + base + (tid & 7)]);

        // B. Poll OWN mailbox (warps 4-7). These are the FIRST loads these
        //    warps issue this iteration -> empty L1tex queue ahead of them.
        if (pollw) {
            const int i = tid & 127;                       // float4 index 0..127
            const float4* p = mybox + (s & (DEPTH - 1)) * (H_DIM / 4) + i;
            float4 a = ld_vol_f4(p);
            if (a.x == SENTINEL || a.y == SENTINEL || a.z == SENTINEL || a.w == SENTINEL) {
                float4 b2 = ld_vol_f4(p);
                while (a.x == SENTINEL || a.y == SENTINEL || a.z == SENTINEL || a.w == SENTINEL) {
                    a = b2;
                    b2 = ld_vol_f4(p);
                }
            }
            ((float4*)sh)[i] = a;
            st_vol_f4((float4*)p, sent4);                  // reset for reuse at s+8
        }
        __syncthreads();

        // C. NOW issue next-step weight prefetch (a full step to complete;
        //    never queues ahead of any poll load).
        {
            const float4* p = (const float4*)(W_hh + ((size_t)stags[sn] * G_DIM + row) * H_DIM) + lane16;
            #pragma unroll
            for (int m = 0; m < 8; m++) wn[m] = __ldg(p + m * 16);
        }
        if (tid < 32) sgin[(s + 1) & 1][tid] = gin_next;

        // D. Dot: 16 lanes per row, 8 float4-FMA groups each (conflict-free)
        const float4* sh4 = (const float4*)sh;
        float a0 = 0.f, a1 = 0.f;
        #pragma unroll
        for (int m = 0; m < 8; m += 2) {
            float4 hA = sh4[lane16 + (m + 0) * 16];
            float4 hB = sh4[lane16 + (m + 1) * 16];
            a0 += wc[m+0].x * hA.x + wc[m+0].y * hA.y + wc[m+0].z * hA.z + wc[m+0].w * hA.w;
            a1 += wc[m+1].x * hB.x + wc[m+1].y * hB.y + wc[m+1].z * hB.z + wc[m+1].w * hB.w;
        }
        float acc = a0 + a1;
        #pragma unroll
        for (int off = 8; off; off >>= 1)
            acc += __shfl_down_sync(0xffffffffu, acc, off, 16);
        if (lane16 == 0) ssum[rid] = acc;
        __syncthreads();

        // E. Warp 0: nonlinearity (lanes 0-7, overflow-safe MUFU) + BROADCAST
        //    h[s+1] into every consumer's private mailbox.
        if (tid < 32) {
            if (tid < 8) {
                float zi = sgin[s & 1][tid]      + ssum[tid];
                float zf = sgin[s & 1][8  + tid] + ssum[8  + tid];
                float zg = sgin[s & 1][16 + tid] + ssum[16 + tid];
                float zo = sgin[s & 1][24 + tid] + ssum[24 + tid];
                float iv = __fdividef(1.f, 1.f + __expf(-zi));
                float fv = __fdividef(1.f, 1.f + __expf(-zf));
                float eg = __expf(-2.f * fabsf(zg));
                float gv = copysignf(__fdividef(1.f - eg, 1.f + eg), zg);
                float ov = __fdividef(1.f, 1.f + __expf(-zo));
                cval = fv * cval + iv * gv;
                float ec = __expf(-2.f * fabsf(cval));
                hval = ov * copysignf(__fdividef(1.f - ec, 1.f + ec), cval);
            }
            // collect the 8 fresh h values into every lane of warp 0
            float h0_ = __shfl_sync(0xffffffffu, hval, 0);
            float h1_ = __shfl_sync(0xffffffffu, hval, 1);
            float h2_ = __shfl_sync(0xffffffffu, hval, 2);
            float h3_ = __shfl_sync(0xffffffffu, hval, 3);
            float h4_ = __shfl_sync(0xffffffffu, hval, 4);
            float h5_ = __shfl_sync(0xffffffffu, hval, 5);
            float h6_ = __shfl_sync(0xffffffffu, hval, 6);
            float h7_ = __shfl_sync(0xffffffffu, hval, 7);
            float4 lo = make_float4(h0_, h1_, h2_, h3_);
            float4 hi = make_float4(h4_, h5_, h6_, h7_);
            const int b = (s + 1) & (DEPTH - 1);
            #pragma unroll
            for (int cc = 0; cc < 2; cc++) {
                int cons = tid + cc * 32;                  // 2 consumers per lane
                float4* dst = (float4*)(g_box + ((size_t)cons * DEPTH + b) * H_DIM + base);
                st_vol_f4(dst,     lo);
                st_vol_f4(dst + 1, hi);
            }
        }
        #pragma unroll
        for (int m = 0; m < 8; m++) wc[m] = wn[m];
    }

    // Output layout: [out(1), h(512), c(512)] — h/c only if harness sized it so
    if (tid < UNITS && out_size >= 1 + 2 * H_DIM) {
        d_out[1 + base + tid]         = hval;
        d_out[1 + H_DIM + base + tid] = cval;
    }

    // Block 0: out = sigmoid(h_T . fc_w + fc_b). h_T lives (unconsumed) in
    // block 0's mailbox buffer (T_STEPS & 7).
    if (blockIdx.x == 0) {
        const float* hp = g_box + (size_t)(T_STEPS & (DEPTH - 1)) * H_DIM;  // cons 0
        float v = ld_vol_f(&hp[tid]);
        while (v == SENTINEL) v = ld_vol_f(&hp[tid]);
        v *= __ldg(&fc_w[tid]);
        #pragma unroll
        for (int off = 16; off; off >>= 1) v += __shfl_down_sync(0xffffffffu, v, off);
        if ((tid & 31) == 0) ssum[tid >> 5] = v;          // 16 warps
        __syncthreads();
        if (tid < 16) {
            v = ssum[tid];
            #pragma unroll
            for (int off = 8; off; off >>= 1) v += __shfl_down_sync(0xffffu, v, off, 16);
            if (tid == 0) d_out[0] = __fdividef(1.f, 1.f + __expf(-(v + fc_b[0])));
        }
    }
}

// ---------------------------------------------------------------------------
// Launch. Input order: x, tags, h0, c0, emb, W_ih, W_hh, b_ih, b_hh, fc_w, fc_b.
// ---------------------------------------------------------------------------
extern "C" void kernel_launch(void* const* d_in, const int* in_sizes, int n_in,
                              void* d_out, int out_size)
{
    const int*   x32  = (const int*)  d_in[0];   // int32 OR int64 (device probe)
    const int*   tags = (const int*)  d_in[1];
    const float* h0   = (const float*)d_in[2];
    const float* c0   = (const float*)d_in[3];
    const float* emb  = (const float*)d_in[4];
    const float* W_ih = (const float*)d_in[5];
    const float* W_hh = (const float*)d_in[6];
    const float* b_ih = (const float*)d_in[7];
    const float* b_hh = (const float*)d_in[8];
    const float* fc_w = (const float*)d_in[9];
    const float* fc_b = (const float*)d_in[10];
    float* out = (float*)d_out;

    init_kernel<<<(NCTA * DEPTH * H_DIM + 511) / 512, 512>>>(h0);
    gates_kernel<<<N_EXP * (G_DIM / ROWS_PER_BLK), 256>>>(x32, tags, emb, W_ih, b_ih, b_hh);
    lstm_kernel<<<NCTA, NTHR>>>(tags, W_hh, c0, fc_w, fc_b, out, out_size);
}

// round 13
// speedup vs baseline: 1.4944x; 1.4944x over previous
#include <cuda_runtime.h>
#include <cstdint>

#define T_STEPS 300
#define E_DIM   300
#define H_DIM   512
#define G_DIM   2048   // 4*H
#define N_EXP   13
#define V_SIZE  400000
#define NCTA    64     // recurrent CTAs; 8 hidden units each
#define UNITS   8
#define NTHR    512
#define DEPTH   8      // mailbox ring depth (power of 2)
#define ROWS_PER_BLK 32
#define SENTINEL 2.0f  // |h| <= 1 always

// Scratch (device globals: no allocation allowed)
__device__ float g_gates[T_STEPS * G_DIM];                       // input gates (+biases)
__device__ __align__(16) float g_box[NCTA * DEPTH * H_DIM];      // private mailboxes, 1 MB

// ---------------------------------------------------------------------------
// Global access helpers
// ---------------------------------------------------------------------------
__device__ __forceinline__ float ld_vol_f(const float* p) {
    float v;
    asm volatile("ld.volatile.global.f32 %0, [%1];" : "=f"(v) : "l"(p));
    return v;
}
__device__ __forceinline__ float4 ld_vol_f4(const float4* p) {
    float4 v;
    asm volatile("ld.volatile.global.v4.f32 {%0,%1,%2,%3}, [%4];"
                 : "=f"(v.x), "=f"(v.y), "=f"(v.z), "=f"(v.w) : "l"(p));
    return v;
}
__device__ __forceinline__ void st_vol_f4(float4* p, float4 v) {
    asm volatile("st.volatile.global.v4.f32 [%0], {%1,%2,%3,%4};"
                 :: "l"(p), "f"(v.x), "f"(v.y), "f"(v.z), "f"(v.w));
}
// Relaxed L2-write publish store: single 16B transaction = data-as-flag unit.
__device__ __forceinline__ void st_cg_f4(float4* p, float4 v) {
    asm volatile("st.global.cg.v4.f32 [%0], {%1,%2,%3,%4};"
                 :: "l"(p), "f"(v.x), "f"(v.y), "f"(v.z), "f"(v.w) : "memory");
}

// ---------------------------------------------------------------------------
// Kernel 1: re-init mailboxes each replay. Depth 0 = h0; others = sentinel.
// ---------------------------------------------------------------------------
__global__ void init_kernel(const float* __restrict__ h0) {
    int idx = blockIdx.x * blockDim.x + threadIdx.x;
    if (idx < NCTA * DEPTH * H_DIM) {
        int k = idx & (H_DIM - 1);
        int d = (idx >> 9) & (DEPTH - 1);
        g_box[idx] = (d == 0) ? h0[k] : SENTINEL;
    }
}

// ---------------------------------------------------------------------------
// x-buffer probe: reference declares int64 but JAX w/o x64 yields int32.
// ---------------------------------------------------------------------------
__device__ __forceinline__ bool probe_is_i64(const int* __restrict__ x32) {
    bool all_zero = true;
    #pragma unroll
    for (int i = 1; i < 64; i += 2) all_zero &= (x32[i] == 0);
    return all_zero;
}
__device__ __forceinline__ int load_token(const int* __restrict__ x32, int t, bool i64) {
    int v = i64 ? x32[2 * t] : x32[t];
    return (v < 0) ? 0 : (v >= V_SIZE ? V_SIZE - 1 : v);
}

// ---------------------------------------------------------------------------
// Kernel 2: input gates (unchanged; proven).
// ---------------------------------------------------------------------------
__global__ void __launch_bounds__(256) gates_kernel(
    const int* __restrict__ x32, const int* __restrict__ tags,
    const float* __restrict__ emb, const float* __restrict__ W_ih,
    const float* __restrict__ b_ih, const float* __restrict__ b_hh)
{
    __shared__ float sw[ROWS_PER_BLK * E_DIM];   // 37.5 KB
    __shared__ float sx[E_DIM];
    __shared__ float sb[ROWS_PER_BLK];
    __shared__ int   stags[T_STEPS];
    __shared__ int   s_i64;

    const int e     = blockIdx.x / (G_DIM / ROWS_PER_BLK);
    const int chunk = blockIdx.x % (G_DIM / ROWS_PER_BLK);
    const int row0  = chunk * ROWS_PER_BLK;
    const int tid   = threadIdx.x;

    const float* wsrc = W_ih + ((size_t)e * G_DIM + row0) * E_DIM;
    for (int i = tid; i < ROWS_PER_BLK * E_DIM; i += 256) sw[i] = wsrc[i];
    if (tid < ROWS_PER_BLK)
        sb[tid] = b_ih[e * G_DIM + row0 + tid] + b_hh[e * G_DIM + row0 + tid];
    for (int i = tid; i < T_STEPS; i += 256) stags[i] = tags[i];
    if (tid == 0) s_i64 = probe_is_i64(x32) ? 1 : 0;
    __syncthreads();

    const bool i64  = (s_i64 != 0);
    const int row   = tid >> 3;   // 0..31
    const int lane8 = tid & 7;

    for (int t = 0; t < T_STEPS; t++) {
        if (stags[t] != e) continue;                 // uniform branch (smem)
        const float* xe = emb + (size_t)load_token(x32, t, i64) * E_DIM;
        for (int i = tid; i < E_DIM; i += 256) sx[i] = xe[i];
        __syncthreads();
        float acc = 0.f;
        for (int k = lane8; k < E_DIM; k += 8)
            acc += sw[row * E_DIM + k] * sx[k];
        #pragma unroll
        for (int off = 4; off; off >>= 1)
            acc += __shfl_down_sync(0xffffffffu, acc, off, 8);
        if (lane8 == 0)
            g_gates[t * G_DIM + row0 + row] = acc + sb[row];
        __syncthreads();
    }
}

// ---------------------------------------------------------------------------
// Kernel 3: recurrent LSTM, 64 CTAs x 512 threads, private-mailbox sync.
// R12 change vs R9 (738us): publish is PARALLEL — warp 0 hands fresh h to
// smem, then 128 threads each issue exactly ONE relaxed st.cg.v4 to one
// (consumer, half) mailbox slot, collapsing the serial volatile-store chain.
// ---------------------------------------------------------------------------
__global__ void __launch_bounds__(NTHR, 1) lstm_kernel(
    const int* __restrict__ tags, const float* __restrict__ W_hh,
    const float* __restrict__ c0,
    const float* __restrict__ fc_w, const float* __restrict__ fc_b,
    float* __restrict__ d_out, int out_size)
{
    __shared__ __align__(16) float sh[H_DIM];   // h[s] staged
    __shared__ float ssum[32];                  // per-row dot sums
    __shared__ float sgin[32];                  // input gates (warp-0 private)
    __shared__ float shnew[UNITS];              // fresh h handoff for publish
    __shared__ int   stags[T_STEPS];

    const int tid    = threadIdx.x;
    const int base   = blockIdx.x * UNITS;      // first hidden unit owned
    const int rid    = tid >> 4;                // 0..31: gate row id
    const int lane16 = tid & 15;
    const int g      = rid >> 3;                // gate: 0=i 1=f 2=g 3=o
    const int u      = rid & 7;                 // unit within CTA
    const int row    = g * H_DIM + base + u;    // global gate row

    for (int i = tid; i < T_STEPS; i += NTHR) stags[i] = tags[i];
    float cval = 0.f, hval = 0.f;
    if (tid < UNITS) cval = c0[base + tid];
    __syncthreads();

    // Preload step-0 weights: thread covers k = lane16*4 + 64*m, m=0..7
    float4 wc[8], wn[8];
    {
        const float4* p = (const float4*)(W_hh + ((size_t)stags[0] * G_DIM + row) * H_DIM) + lane16;
        #pragma unroll
        for (int m = 0; m < 8; m++) wc[m] = __ldg(p + m * 16);
    }

    float4* const mybox = (float4*)(g_box + (size_t)blockIdx.x * DEPTH * H_DIM);
    const float4 sent4 = make_float4(SENTINEL, SENTINEL, SENTINEL, SENTINEL);

    for (int s = 0; s < T_STEPS; s++) {
        // 1. Prefetch next step's weights (tag known -> hides L2 latency)
        {
            int sn = (s + 1 < T_STEPS) ? s + 1 : s;
            const float4* p = (const float4*)(W_hh + ((size_t)stags[sn] * G_DIM + row) * H_DIM) + lane16;
            #pragma unroll
            for (int m = 0; m < 8; m++) wn[m] = __ldg(p + m * 16);
        }
        // 2. Input gates for this step (warp 0 writes, warp 0 reads: no race)
        if (tid < 32)
            sgin[tid] = __ldg(&g_gates[s * G_DIM + (tid >> 3) * H_DIM + base + (tid & 7)]);

        // 3. Poll OWN mailbox (warps 4-7; private region -> contention-free).
        //    2-deep rotated pipeline: check lands on an already-completed load.
        if ((tid >> 7) == 1) {
            const int i = tid & 127;                       // float4 index 0..127
            const float4* p = mybox + (s & (DEPTH - 1)) * (H_DIM / 4) + i;
            float4 a = ld_vol_f4(p);
            if (a.x == SENTINEL || a.y == SENTINEL || a.z == SENTINEL || a.w == SENTINEL) {
                float4 b2 = ld_vol_f4(p);
                while (a.x == SENTINEL || a.y == SENTINEL || a.z == SENTINEL || a.w == SENTINEL) {
                    a = b2;
                    b2 = ld_vol_f4(p);
                }
            }
            ((float4*)sh)[i] = a;
            st_vol_f4((float4*)p, sent4);                  // reset for reuse at s+8
        }
        __syncthreads();

        // 4. Dot: 16 lanes per row, 8 float4-FMA groups each (conflict-free)
        const float4* sh4 = (const float4*)sh;
        float a0 = 0.f, a1 = 0.f;
        #pragma unroll
        for (int m = 0; m < 8; m += 2) {
            float4 hA = sh4[lane16 + (m + 0) * 16];
            float4 hB = sh4[lane16 + (m + 1) * 16];
            a0 += wc[m+0].x * hA.x + wc[m+0].y * hA.y + wc[m+0].z * hA.z + wc[m+0].w * hA.w;
            a1 += wc[m+1].x * hB.x + wc[m+1].y * hB.y + wc[m+1].z * hB.z + wc[m+1].w * hB.w;
        }
        float acc = a0 + a1;
        #pragma unroll
        for (int off = 8; off; off >>= 1)
            acc += __shfl_down_sync(0xffffffffu, acc, off, 16);
        if (lane16 == 0) ssum[rid] = acc;
        __syncthreads();

        // 5. Warp 0 lanes 0-7: nonlinearity (overflow-safe MUFU) -> smem handoff
        if (tid < 8) {
            float zi = sgin[tid]      + ssum[tid];
            float zf = sgin[8  + tid] + ssum[8  + tid];
            float zg = sgin[16 + tid] + ssum[16 + tid];
            float zo = sgin[24 + tid] + ssum[24 + tid];
            float iv = __fdividef(1.f, 1.f + __expf(-zi));
            float fv = __fdividef(1.f, 1.f + __expf(-zf));
            float eg = __expf(-2.f * fabsf(zg));
            float gv = copysignf(__fdividef(1.f - eg, 1.f + eg), zg);
            float ov = __fdividef(1.f, 1.f + __expf(-zo));
            cval = fv * cval + iv * gv;
            float ec = __expf(-2.f * fabsf(cval));
            hval = ov * copysignf(__fdividef(1.f - ec, 1.f + ec), cval);
            shnew[tid] = hval;
        }
        __syncthreads();

        // 6. PARALLEL publish: 128 threads (warps 0-3), one st.cg.v4 each ->
        //    all 64 consumer mailboxes written concurrently, no serial chain.
        if (tid < 128) {
            const int cons = tid >> 1;
            const int half = tid & 1;
            float4 v = make_float4(shnew[half * 4 + 0], shnew[half * 4 + 1],
                                   shnew[half * 4 + 2], shnew[half * 4 + 3]);
            const int b = (s + 1) & (DEPTH - 1);
            float4* dst = (float4*)(g_box + ((size_t)cons * DEPTH + b) * H_DIM + base) + half;
            st_cg_f4(dst, v);
        }
        #pragma unroll
        for (int m = 0; m < 8; m++) wc[m] = wn[m];
    }

    // Output layout: [out(1), h(512), c(512)] — h/c only if harness sized it so
    if (tid < UNITS && out_size >= 1 + 2 * H_DIM) {
        d_out[1 + base + tid]         = hval;
        d_out[1 + H_DIM + base + tid] = cval;
    }

    // Block 0: out = sigmoid(h_T . fc_w + fc_b). h_T lives (unconsumed) in
    // block 0's mailbox buffer (T_STEPS & 7).
    if (blockIdx.x == 0) {
        const float* hp = g_box + (size_t)(T_STEPS & (DEPTH - 1)) * H_DIM;  // cons 0
        float v = ld_vol_f(&hp[tid]);
        while (v == SENTINEL) v = ld_vol_f(&hp[tid]);
        v *= __ldg(&fc_w[tid]);
        #pragma unroll
        for (int off = 16; off; off >>= 1) v += __shfl_down_sync(0xffffffffu, v, off);
        if ((tid & 31) == 0) ssum[tid >> 5] = v;          // 16 warps
        __syncthreads();
        if (tid < 16) {
            v = ssum[tid];
            #pragma unroll
            for (int off = 8; off; off >>= 1) v += __shfl_down_sync(0xffffu, v, off, 16);
            if (tid == 0) d_out[0] = __fdividef(1.f, 1.f + __expf(-(v + fc_b[0])));
        }
    }
}

// ---------------------------------------------------------------------------
// Launch. Input order: x, tags, h0, c0, emb, W_ih, W_hh, b_ih, b_hh, fc_w, fc_b.
// ---------------------------------------------------------------------------
extern "C" void kernel_launch(void* const* d_in, const int* in_sizes, int n_in,
                              void* d_out, int out_size)
{
    const int*   x32  = (const int*)  d_in[0];   // int32 OR int64 (device probe)
    const int*   tags = (const int*)  d_in[1];
    const float* h0   = (const float*)d_in[2];
    const float* c0   = (const float*)d_in[3];
    const float* emb  = (const float*)d_in[4];
    const float* W_ih = (const float*)d_in[5];
    const float* W_hh = (const float*)d_in[6];
    const float* b_ih = (const float*)d_in[7];
    const float* b_hh = (const float*)d_in[8];
    const float* fc_w = (const float*)d_in[9];
    const float* fc_b = (const float*)d_in[10];
    float* out = (float*)d_out;

    init_kernel<<<(NCTA * DEPTH * H_DIM + 511) / 512, 512>>>(h0);
    gates_kernel<<<N_EXP * (G_DIM / ROWS_PER_BLK), 256>>>(x32, tags, emb, W_ih, b_ih, b_hh);
    lstm_kernel<<<NCTA, NTHR>>>(tags, W_hh, c0, fc_w, fc_b, out, out_size);
}